// round 1
// baseline (speedup 1.0000x reference)
#include <cuda_runtime.h>
#include <math.h>
#include <float.h>

#define NB 4096
#define TT 200
#define DD 64
#define H1 16
#define H2 8
#define KP 201   // odd pitch -> conflict-free transposed SMEM

#define NEG_INF_F (-4294967296.0f)   // fp32 rounding of -(2^32)+1

__global__ __launch_bounds__(256, 1)
void din_attn_kernel(const float* __restrict__ qg,
                     const float* __restrict__ kg,
                     const int*   __restrict__ lg,
                     const float* __restrict__ W1,
                     const float* __restrict__ b1,
                     const float* __restrict__ W2,
                     const float* __restrict__ b2,
                     const float* __restrict__ W3,
                     const float* __restrict__ b3,
                     const float* __restrict__ W4,
                     const float* __restrict__ b4,
                     float* __restrict__ outg)
{
    extern __shared__ float k_s[];       // [DD][KP] transposed keys, 51456 B
    __shared__ float M_s[DD * H1];       // per-batch effective W1 (64x16)
    __shared__ float sc_s[TT];           // scores -> exp(p)
    __shared__ float q_s[DD];
    __shared__ float v_s[H1];            // per-batch bias for layer 1
    __shared__ float W2_s[H1 * H2];
    __shared__ float b2_s[H2];
    __shared__ float W3_s[H2];
    __shared__ float red_s[8];
    __shared__ float o_s[DD];
    __shared__ float b3_s;

    const int b   = blockIdx.x;
    const int tid = threadIdx.x;

    // ---- tiny parameter loads ----
    if (tid < DD)      q_s[tid]  = qg[(size_t)b * DD + tid];
    if (tid < H1 * H2) W2_s[tid] = W2[tid];
    if (tid < H2)      { b2_s[tid] = b2[tid]; W3_s[tid] = W3[tid]; }
    if (tid == 0)      b3_s = b3[0];
    __syncthreads();

    // ---- keys -> transposed smem (coalesced float4 gmem reads) ----
    const float4* kg4 = reinterpret_cast<const float4*>(kg + (size_t)b * TT * DD);
    #pragma unroll 1
    for (int i = tid; i < (TT * DD) / 4; i += 256) {
        float4 v = kg4[i];
        int idx = i << 2;
        int t = idx >> 6;     // /64
        int d = idx & 63;
        k_s[(d + 0) * KP + t] = v.x;
        k_s[(d + 1) * KP + t] = v.y;
        k_s[(d + 2) * KP + t] = v.z;
        k_s[(d + 3) * KP + t] = v.w;
    }

    // ---- effective per-batch weight: M[d][h] = W1b - W1c + q_d * W1d ----
    for (int i = tid; i < DD * H1; i += 256) {
        int d = i >> 4, h = i & 15;
        M_s[i] = W1[(64 + d) * H1 + h] - W1[(128 + d) * H1 + h]
               + q_s[d] * W1[(192 + d) * H1 + h];
    }
    // ---- per-batch bias: v[h] = b1 + q @ (W1a + W1c) ----
    if (tid < H1) {
        float acc = b1[tid];
        #pragma unroll 8
        for (int d = 0; d < DD; d++)
            acc += q_s[d] * (W1[d * H1 + tid] + W1[(128 + d) * H1 + tid]);
        v_s[tid] = acc;
    }
    __syncthreads();

    const int len = lg[b];

    // ---- pass 1: per-t MLP scorer ----
    float s = -FLT_MAX;
    if (tid < TT) {
        float h[H1];
        #pragma unroll
        for (int j = 0; j < H1; j++) h[j] = v_s[j];

        const float4* M4 = reinterpret_cast<const float4*>(M_s);
        #pragma unroll 4
        for (int d = 0; d < DD; d++) {
            float kd = k_s[d * KP + tid];
            float4 m0 = M4[d * 4 + 0];
            float4 m1 = M4[d * 4 + 1];
            float4 m2 = M4[d * 4 + 2];
            float4 m3 = M4[d * 4 + 3];
            h[0]  = fmaf(kd, m0.x, h[0]);
            h[1]  = fmaf(kd, m0.y, h[1]);
            h[2]  = fmaf(kd, m0.z, h[2]);
            h[3]  = fmaf(kd, m0.w, h[3]);
            h[4]  = fmaf(kd, m1.x, h[4]);
            h[5]  = fmaf(kd, m1.y, h[5]);
            h[6]  = fmaf(kd, m1.z, h[6]);
            h[7]  = fmaf(kd, m1.w, h[7]);
            h[8]  = fmaf(kd, m2.x, h[8]);
            h[9]  = fmaf(kd, m2.y, h[9]);
            h[10] = fmaf(kd, m2.z, h[10]);
            h[11] = fmaf(kd, m2.w, h[11]);
            h[12] = fmaf(kd, m3.x, h[12]);
            h[13] = fmaf(kd, m3.y, h[13]);
            h[14] = fmaf(kd, m3.z, h[14]);
            h[15] = fmaf(kd, m3.w, h[15]);
        }
        #pragma unroll
        for (int j = 0; j < H1; j++) h[j] = 1.0f / (1.0f + expf(-h[j]));

        float x2[H2];
        #pragma unroll
        for (int k = 0; k < H2; k++) {
            float a = b2_s[k];
            #pragma unroll
            for (int j = 0; j < H1; j++) a = fmaf(h[j], W2_s[j * H2 + k], a);
            x2[k] = 1.0f / (1.0f + expf(-a));
        }
        float sc = b3_s;
        #pragma unroll
        for (int k = 0; k < H2; k++) sc = fmaf(x2[k], W3_s[k], sc);

        sc = (tid < len) ? sc : NEG_INF_F;
        s = sc * 0.125f;   // 1/sqrt(64), applied after masking like reference
    }

    // ---- block softmax: max ----
    float val = s;
    #pragma unroll
    for (int o = 16; o; o >>= 1) val = fmaxf(val, __shfl_xor_sync(0xffffffffu, val, o));
    if ((tid & 31) == 0) red_s[tid >> 5] = val;
    __syncthreads();
    float mx = red_s[0];
    #pragma unroll
    for (int i = 1; i < 8; i++) mx = fmaxf(mx, red_s[i]);
    __syncthreads();   // everyone done reading red_s before reuse

    // ---- exp + sum ----
    float p = 0.0f;
    if (tid < TT) { p = expf(s - mx); sc_s[tid] = p; }
    float sv = p;
    #pragma unroll
    for (int o = 16; o; o >>= 1) sv += __shfl_xor_sync(0xffffffffu, sv, o);
    if ((tid & 31) == 0) red_s[tid >> 5] = sv;
    __syncthreads();
    float denom = 0.0f;
    #pragma unroll
    for (int i = 0; i < 8; i++) denom += red_s[i];
    float inv = 1.0f / denom;

    // ---- pass 2: weighted key sum (threads 0..63, one per d) ----
    if (tid < DD) {
        float acc = 0.0f;
        #pragma unroll 4
        for (int t = 0; t < TT; t++)
            acc = fmaf(sc_s[t], k_s[tid * KP + t], acc);
        o_s[tid] = acc * inv;
    }
    __syncthreads();

    // ---- output projection: out = o @ W4 + b4 ----
    if (tid < DD) {
        float acc = b4[tid];
        #pragma unroll 8
        for (int d = 0; d < DD; d++)
            acc = fmaf(o_s[d], W4[d * DD + tid], acc);
        outg[(size_t)b * DD + tid] = acc;
    }
}

extern "C" void kernel_launch(void* const* d_in, const int* in_sizes, int n_in,
                              void* d_out, int out_size)
{
    const float* q  = (const float*)d_in[0];
    const float* k  = (const float*)d_in[1];
    const int*   l  = (const int*)d_in[2];
    const float* W1 = (const float*)d_in[3];
    const float* b1 = (const float*)d_in[4];
    const float* W2 = (const float*)d_in[5];
    const float* b2 = (const float*)d_in[6];
    const float* W3 = (const float*)d_in[7];
    const float* b3 = (const float*)d_in[8];
    const float* W4 = (const float*)d_in[9];
    const float* b4 = (const float*)d_in[10];
    float* out = (float*)d_out;

    const int smem_bytes = DD * KP * sizeof(float);   // 51456 B dynamic
    cudaFuncSetAttribute(din_attn_kernel,
                         cudaFuncAttributeMaxDynamicSharedMemorySize, smem_bytes);

    din_attn_kernel<<<NB, 256, smem_bytes>>>(q, k, l, W1, b1, W2, b2,
                                             W3, b3, W4, b4, out);
}

// round 3
// speedup vs baseline: 1.7893x; 1.7893x over previous
#include <cuda_runtime.h>
#include <cstdint>
#include <math.h>
#include <float.h>

#define NB 4096
#define TT 200
#define DD 64
#define H1 16
#define H2 8
#define KP 68    // pitch in floats: 272B rows, 16B aligned, conflict-free both passes

#define NEG_INF_F (-4294967296.0f)   // fp32 rounding of -(2^32)+1

__device__ __forceinline__ void cp_async16(uint32_t smem_dst, const void* gsrc) {
    asm volatile("cp.async.cg.shared.global [%0], [%1], 16;\n"
                 :: "r"(smem_dst), "l"(gsrc));
}
__device__ __forceinline__ void cp_async_wait_all() {
    asm volatile("cp.async.wait_all;\n" ::: "memory");
}

__device__ __forceinline__ float fsigmoid(float x) {
    return __fdividef(1.0f, 1.0f + __expf(-x));
}

__global__ __launch_bounds__(256, 3)
void din_attn_kernel(const float* __restrict__ qg,
                     const float* __restrict__ kg,
                     const int*   __restrict__ lg,
                     const float* __restrict__ W1,
                     const float* __restrict__ b1,
                     const float* __restrict__ W2,
                     const float* __restrict__ b2,
                     const float* __restrict__ W3,
                     const float* __restrict__ b3,
                     const float* __restrict__ W4,
                     const float* __restrict__ b4,
                     float* __restrict__ outg)
{
    extern __shared__ float k_s[];       // [TT][KP] keys, natural layout, 54400 B
    __shared__ float M_s[DD * H1];       // per-batch effective W1 (64x16)
    __shared__ float sc_s[TT];           // exp(score - max)
    __shared__ float q_s[DD];
    __shared__ float v_s[H1];            // per-batch layer-1 bias
    __shared__ float W2_s[H1 * H2];
    __shared__ float b2_s[H2];
    __shared__ float W3_s[H2];
    __shared__ float red_s[8];
    __shared__ float o_s[DD];
    __shared__ float op_s[4][DD];        // partial sums (pass2 & projection)
    __shared__ float b3_s;

    const int b   = blockIdx.x;
    const int tid = threadIdx.x;

    // ---- issue ALL key-tile copies asynchronously (deep MLP) ----
    // element i of 3200 float4s: t = i>>4, col = i&15 ; dst = t*272 + col*16 bytes
    {
        const char* gbase = (const char*)(kg + (size_t)b * TT * DD);
        uint32_t sbase = (uint32_t)__cvta_generic_to_shared(k_s);
        #pragma unroll
        for (int it = 0; it < 12; it++) {
            int i = tid + it * 256;
            int t = i >> 4, c = i & 15;
            cp_async16(sbase + t * (KP * 4) + c * 16, gbase + i * 16);
        }
        if (tid < 128) {
            int i = tid + 3072;
            int t = i >> 4, c = i & 15;
            cp_async16(sbase + t * (KP * 4) + c * 16, gbase + i * 16);
        }
    }

    // ---- tiny parameter loads (overlap with async copies) ----
    if (tid < DD)      q_s[tid]  = qg[(size_t)b * DD + tid];
    if (tid >= 64 && tid < 64 + H1 * H2) W2_s[tid - 64] = W2[tid - 64];
    if (tid >= 192 && tid < 192 + H2)    { b2_s[tid - 192] = b2[tid - 192]; W3_s[tid - 192] = W3[tid - 192]; }
    if (tid == 255)    b3_s = b3[0];
    __syncthreads();

    // ---- effective per-batch weight: M[d][h] = W1b - W1c + q_d * W1d ----
    for (int i = tid; i < DD * H1; i += 256) {
        int d = i >> 4, h = i & 15;
        M_s[i] = W1[(64 + d) * H1 + h] - W1[(128 + d) * H1 + h]
               + q_s[d] * W1[(192 + d) * H1 + h];
    }
    // ---- per-batch bias: v[h] = b1 + q @ (W1a + W1c) ----
    if (tid < H1) {
        float a0 = 0.f, a1 = 0.f, a2 = 0.f, a3 = 0.f;
        #pragma unroll 4
        for (int d = 0; d < DD; d += 4) {
            a0 = fmaf(q_s[d + 0], W1[(d + 0) * H1 + tid] + W1[(128 + d + 0) * H1 + tid], a0);
            a1 = fmaf(q_s[d + 1], W1[(d + 1) * H1 + tid] + W1[(128 + d + 1) * H1 + tid], a1);
            a2 = fmaf(q_s[d + 2], W1[(d + 2) * H1 + tid] + W1[(128 + d + 2) * H1 + tid], a2);
            a3 = fmaf(q_s[d + 3], W1[(d + 3) * H1 + tid] + W1[(128 + d + 3) * H1 + tid], a3);
        }
        v_s[tid] = b1[tid] + ((a0 + a1) + (a2 + a3));
    }

    const int len = lg[b];

    cp_async_wait_all();
    __syncthreads();

    // ---- pass 1: per-t MLP scorer (threads 0..199, t = tid) ----
    float s = -FLT_MAX;
    if (tid < TT) {
        float h[H1];
        #pragma unroll
        for (int j = 0; j < H1; j++) h[j] = v_s[j];

        const float4* M4 = reinterpret_cast<const float4*>(M_s);
        const float4* k4 = reinterpret_cast<const float4*>(k_s + tid * KP);
        #pragma unroll 4
        for (int db = 0; db < 16; db++) {       // 4 d's per iteration
            float4 kv = k4[db];
            #pragma unroll
            for (int sub = 0; sub < 4; sub++) {
                float kd = (sub == 0) ? kv.x : (sub == 1) ? kv.y : (sub == 2) ? kv.z : kv.w;
                int d = db * 4 + sub;
                float4 m0 = M4[d * 4 + 0];
                float4 m1 = M4[d * 4 + 1];
                float4 m2 = M4[d * 4 + 2];
                float4 m3 = M4[d * 4 + 3];
                h[0]  = fmaf(kd, m0.x, h[0]);   h[1]  = fmaf(kd, m0.y, h[1]);
                h[2]  = fmaf(kd, m0.z, h[2]);   h[3]  = fmaf(kd, m0.w, h[3]);
                h[4]  = fmaf(kd, m1.x, h[4]);   h[5]  = fmaf(kd, m1.y, h[5]);
                h[6]  = fmaf(kd, m1.z, h[6]);   h[7]  = fmaf(kd, m1.w, h[7]);
                h[8]  = fmaf(kd, m2.x, h[8]);   h[9]  = fmaf(kd, m2.y, h[9]);
                h[10] = fmaf(kd, m2.z, h[10]);  h[11] = fmaf(kd, m2.w, h[11]);
                h[12] = fmaf(kd, m3.x, h[12]);  h[13] = fmaf(kd, m3.y, h[13]);
                h[14] = fmaf(kd, m3.z, h[14]);  h[15] = fmaf(kd, m3.w, h[15]);
            }
        }
        #pragma unroll
        for (int j = 0; j < H1; j++) h[j] = fsigmoid(h[j]);

        float x2[H2];
        #pragma unroll
        for (int k = 0; k < H2; k++) {
            float a = b2_s[k];
            #pragma unroll
            for (int j = 0; j < H1; j++) a = fmaf(h[j], W2_s[j * H2 + k], a);
            x2[k] = fsigmoid(a);
        }
        float sc = b3_s;
        #pragma unroll
        for (int k = 0; k < H2; k++) sc = fmaf(x2[k], W3_s[k], sc);

        sc = (tid < len) ? sc : NEG_INF_F;
        s = sc * 0.125f;   // 1/sqrt(64) after masking, as in reference
    }

    // ---- block softmax max (needed: len==0 must give uniform attention) ----
    float val = s;
    #pragma unroll
    for (int o = 16; o; o >>= 1) val = fmaxf(val, __shfl_xor_sync(0xffffffffu, val, o));
    if ((tid & 31) == 0) red_s[tid >> 5] = val;
    __syncthreads();
    float mx = red_s[0];
    #pragma unroll
    for (int i = 1; i < 8; i++) mx = fmaxf(mx, red_s[i]);
    __syncthreads();

    // ---- exp + sum ----
    float p = 0.0f;
    if (tid < TT) { p = __expf(s - mx); sc_s[tid] = p; }
    float sv = p;
    #pragma unroll
    for (int o = 16; o; o >>= 1) sv += __shfl_xor_sync(0xffffffffu, sv, o);
    if ((tid & 31) == 0) red_s[tid >> 5] = sv;
    __syncthreads();
    float denom = 0.0f;
    #pragma unroll
    for (int i = 0; i < 8; i++) denom += red_s[i];
    float inv = __fdividef(1.0f, denom);

    // ---- pass 2: weighted key sum, all 256 threads (g = t-quarter, d = lane-dim) ----
    {
        int g = tid >> 6, d = tid & 63;
        int t0 = g * 50;
        float a0 = 0.f, a1 = 0.f;
        #pragma unroll 5
        for (int t = 0; t < 50; t += 2) {
            a0 = fmaf(sc_s[t0 + t],     k_s[(t0 + t)     * KP + d], a0);
            a1 = fmaf(sc_s[t0 + t + 1], k_s[(t0 + t + 1) * KP + d], a1);
        }
        op_s[g][d] = a0 + a1;
    }
    __syncthreads();
    if (tid < DD)
        o_s[tid] = (op_s[0][tid] + op_s[1][tid] + op_s[2][tid] + op_s[3][tid]) * inv;
    __syncthreads();

    // ---- projection partials: thread (g,d) sums dp in [g*16, g*16+16) ----
    {
        int g = tid >> 6, d = tid & 63;
        int dp0 = g * 16;
        float a0 = 0.f, a1 = 0.f;
        #pragma unroll
        for (int dp = 0; dp < 16; dp += 2) {
            a0 = fmaf(o_s[dp0 + dp],     W4[(dp0 + dp)     * DD + d], a0);
            a1 = fmaf(o_s[dp0 + dp + 1], W4[(dp0 + dp + 1) * DD + d], a1);
        }
        op_s[g][d] = a0 + a1;
    }
    __syncthreads();
    if (tid < DD)
        outg[(size_t)b * DD + tid] =
            (op_s[0][tid] + op_s[1][tid]) + (op_s[2][tid] + op_s[3][tid]) + b4[tid];
}

extern "C" void kernel_launch(void* const* d_in, const int* in_sizes, int n_in,
                              void* d_out, int out_size)
{
    const float* q  = (const float*)d_in[0];
    const float* k  = (const float*)d_in[1];
    const int*   l  = (const int*)d_in[2];
    const float* W1 = (const float*)d_in[3];
    const float* b1 = (const float*)d_in[4];
    const float* W2 = (const float*)d_in[5];
    const float* b2 = (const float*)d_in[6];
    const float* W3 = (const float*)d_in[7];
    const float* b3 = (const float*)d_in[8];
    const float* W4 = (const float*)d_in[9];
    const float* b4 = (const float*)d_in[10];
    float* out = (float*)d_out;

    const int smem_bytes = TT * KP * sizeof(float);   // 54400 B dynamic
    cudaFuncSetAttribute(din_attn_kernel,
                         cudaFuncAttributeMaxDynamicSharedMemorySize, smem_bytes);

    din_attn_kernel<<<NB, 256, smem_bytes>>>(q, k, l, W1, b1, W2, b2,
                                             W3, b3, W4, b4, out);
}

// round 4
// speedup vs baseline: 2.2478x; 1.2563x over previous
#include <cuda_runtime.h>
#include <cstdint>
#include <math.h>
#include <float.h>

#define NB 4096
#define TT 200
#define DD 64
#define H1 16
#define H2 8
#define KP 68    // pitch in floats: 272B rows, 16B aligned, conflict-free

#define NEG_INF_F (-4294967296.0f)   // fp32 rounding of -(2^32)+1

typedef unsigned long long ull;

__device__ __forceinline__ void cp_async16(uint32_t smem_dst, const void* gsrc) {
    asm volatile("cp.async.cg.shared.global [%0], [%1], 16;\n"
                 :: "r"(smem_dst), "l"(gsrc));
}
__device__ __forceinline__ void cp_async_wait_all() {
    asm volatile("cp.async.wait_all;\n" ::: "memory");
}
__device__ __forceinline__ float fsigmoid(float x) {
    return __fdividef(1.0f, 1.0f + __expf(-x));
}
// ---- packed f32x2 helpers ----
__device__ __forceinline__ ull pack2(float x, float y) {
    ull r; asm("mov.b64 %0, {%1, %2};" : "=l"(r) : "f"(x), "f"(y)); return r;
}
__device__ __forceinline__ void unpack2(ull v, float& x, float& y) {
    asm("mov.b64 {%0, %1}, %2;" : "=f"(x), "=f"(y) : "l"(v));
}
__device__ __forceinline__ ull fma2(ull a, ull b, ull c) {
    ull d; asm("fma.rn.f32x2 %0, %1, %2, %3;" : "=l"(d) : "l"(a), "l"(b), "l"(c));
    return d;
}
__device__ __forceinline__ void lds_v2u64(uint32_t saddr, ull& a, ull& b) {
    asm volatile("ld.shared.v2.u64 {%0, %1}, [%2];"
                 : "=l"(a), "=l"(b) : "r"(saddr));
}

__global__ __launch_bounds__(256, 3)
void din_attn_kernel(const float* __restrict__ qg,
                     const float* __restrict__ kg,
                     const int*   __restrict__ lg,
                     const float* __restrict__ W1,
                     const float* __restrict__ b1,
                     const float* __restrict__ W2,
                     const float* __restrict__ b2,
                     const float* __restrict__ W3,
                     const float* __restrict__ b3,
                     const float* __restrict__ W4,
                     const float* __restrict__ b4,
                     float* __restrict__ outg)
{
    extern __shared__ float k_s[];                 // [TT][KP] keys, 54400 B
    __shared__ __align__(16) float M_s[DD * H1];   // per-batch effective W1 (64x16)
    __shared__ float sc_s[TT];                     // exp(score - max)
    __shared__ float q_s[DD];
    __shared__ float v_s[H1];
    __shared__ float W2_s[H1 * H2];
    __shared__ float b2_s[H2];
    __shared__ float W3_s[H2];
    __shared__ float red_s[8];
    __shared__ float o_s[DD];
    __shared__ __align__(16) float op_s[8][DD];    // partials (pass2 & projection)
    __shared__ float b3_s;

    const int b   = blockIdx.x;
    const int tid = threadIdx.x;

    // ---- issue ALL key-tile copies asynchronously (deep MLP) ----
    {
        const char* gbase = (const char*)(kg + (size_t)b * TT * DD);
        uint32_t sbase = (uint32_t)__cvta_generic_to_shared(k_s);
        #pragma unroll
        for (int it = 0; it < 12; it++) {
            int i = tid + it * 256;
            int t = i >> 4, c = i & 15;
            cp_async16(sbase + t * (KP * 4) + c * 16, gbase + i * 16);
        }
        if (tid < 128) {
            int i = tid + 3072;
            int t = i >> 4, c = i & 15;
            cp_async16(sbase + t * (KP * 4) + c * 16, gbase + i * 16);
        }
    }

    // ---- tiny parameter loads (overlap with async copies) ----
    if (tid < DD)      q_s[tid]  = qg[(size_t)b * DD + tid];
    if (tid >= 64 && tid < 64 + H1 * H2) W2_s[tid - 64] = W2[tid - 64];
    if (tid >= 192 && tid < 192 + H2)    { b2_s[tid - 192] = b2[tid - 192]; W3_s[tid - 192] = W3[tid - 192]; }
    if (tid == 255)    b3_s = b3[0];
    __syncthreads();

    // ---- effective per-batch weight: M[d][h] = W1b - W1c + q_d * W1d ----
    for (int i = tid; i < DD * H1; i += 256) {
        int d = i >> 4, h = i & 15;
        M_s[i] = W1[(64 + d) * H1 + h] - W1[(128 + d) * H1 + h]
               + q_s[d] * W1[(192 + d) * H1 + h];
    }
    // ---- per-batch bias: v[h] = b1 + q @ (W1a + W1c) ----
    if (tid < H1) {
        float a0 = 0.f, a1 = 0.f;
        #pragma unroll 8
        for (int d = 0; d < DD; d += 2) {
            a0 = fmaf(q_s[d + 0], W1[(d + 0) * H1 + tid] + W1[(128 + d + 0) * H1 + tid], a0);
            a1 = fmaf(q_s[d + 1], W1[(d + 1) * H1 + tid] + W1[(128 + d + 1) * H1 + tid], a1);
        }
        v_s[tid] = b1[tid] + a0 + a1;
    }

    const int len = lg[b];

    cp_async_wait_all();
    __syncthreads();

    // ---- pass 1: MLP scorer, thread i<100 handles t0=i and t1=i+100 ----
    float s0 = -FLT_MAX, s1 = -FLT_MAX;
    if (tid < 100) {
        const int t0 = tid, t1 = tid + 100;
        ull acc0[8], acc1[8];
        #pragma unroll
        for (int j = 0; j < 8; j++) {
            ull v = pack2(v_s[2 * j], v_s[2 * j + 1]);
            acc0[j] = v; acc1[j] = v;
        }

        const float4* k40 = reinterpret_cast<const float4*>(k_s + t0 * KP);
        const float4* k41 = reinterpret_cast<const float4*>(k_s + t1 * KP);
        const uint32_t Mb = (uint32_t)__cvta_generic_to_shared(M_s);

        #pragma unroll 4
        for (int db = 0; db < 16; db++) {
            float4 ka = k40[db];
            float4 kb = k41[db];
            #pragma unroll
            for (int sub = 0; sub < 4; sub++) {
                float a = (sub == 0) ? ka.x : (sub == 1) ? ka.y : (sub == 2) ? ka.z : ka.w;
                float c = (sub == 0) ? kb.x : (sub == 1) ? kb.y : (sub == 2) ? kb.z : kb.w;
                ull kpa = pack2(a, a);
                ull kpb = pack2(c, c);
                uint32_t off = Mb + (db * 4 + sub) * 64;
                ull m[8];
                lds_v2u64(off +  0, m[0], m[1]);
                lds_v2u64(off + 16, m[2], m[3]);
                lds_v2u64(off + 32, m[4], m[5]);
                lds_v2u64(off + 48, m[6], m[7]);
                #pragma unroll
                for (int j = 0; j < 8; j++) acc0[j] = fma2(kpa, m[j], acc0[j]);
                #pragma unroll
                for (int j = 0; j < 8; j++) acc1[j] = fma2(kpb, m[j], acc1[j]);
            }
        }

        // tail MLP for both t's
        #pragma unroll
        for (int which = 0; which < 2; which++) {
            float h[H1];
            #pragma unroll
            for (int j = 0; j < 8; j++)
                unpack2(which ? acc1[j] : acc0[j], h[2 * j], h[2 * j + 1]);
            #pragma unroll
            for (int j = 0; j < H1; j++) h[j] = fsigmoid(h[j]);

            float x2[H2];
            #pragma unroll
            for (int k = 0; k < H2; k++) {
                float acc = b2_s[k];
                #pragma unroll
                for (int j = 0; j < H1; j++) acc = fmaf(h[j], W2_s[j * H2 + k], acc);
                x2[k] = fsigmoid(acc);
            }
            float sc = b3_s;
            #pragma unroll
            for (int k = 0; k < H2; k++) sc = fmaf(x2[k], W3_s[k], sc);

            if (which == 0) { sc = (t0 < len) ? sc : NEG_INF_F; s0 = sc * 0.125f; }
            else            { sc = (t1 < len) ? sc : NEG_INF_F; s1 = sc * 0.125f; }
        }
    }

    // ---- block softmax max (len==0 must give uniform attention) ----
    float val = fmaxf(s0, s1);
    #pragma unroll
    for (int o = 16; o; o >>= 1) val = fmaxf(val, __shfl_xor_sync(0xffffffffu, val, o));
    if ((tid & 31) == 0) red_s[tid >> 5] = val;
    __syncthreads();
    float mx = red_s[0];
    #pragma unroll
    for (int i = 1; i < 8; i++) mx = fmaxf(mx, red_s[i]);
    __syncthreads();

    // ---- exp + sum ----
    float p = 0.0f;
    if (tid < 100) {
        float p0 = __expf(s0 - mx);
        float p1 = __expf(s1 - mx);
        sc_s[tid]       = p0;
        sc_s[tid + 100] = p1;
        p = p0 + p1;
    }
    #pragma unroll
    for (int o = 16; o; o >>= 1) p += __shfl_xor_sync(0xffffffffu, p, o);
    if ((tid & 31) == 0) red_s[tid >> 5] = p;
    __syncthreads();
    float denom = 0.0f;
    #pragma unroll
    for (int i = 0; i < 8; i++) denom += red_s[i];
    float inv = __fdividef(1.0f, denom);

    // ---- pass 2: weighted key sum; 128 threads = 8 t-groups x 16 d-quads ----
    if (tid < 128) {
        int g = tid >> 4, dq = (tid & 15) * 4;
        int tb = g * 25;
        float4 acc = make_float4(0.f, 0.f, 0.f, 0.f);
        #pragma unroll 5
        for (int i = 0; i < 25; i++) {
            float w = sc_s[tb + i];
            float4 kv = *reinterpret_cast<const float4*>(k_s + (tb + i) * KP + dq);
            acc.x = fmaf(w, kv.x, acc.x);
            acc.y = fmaf(w, kv.y, acc.y);
            acc.z = fmaf(w, kv.z, acc.z);
            acc.w = fmaf(w, kv.w, acc.w);
        }
        *reinterpret_cast<float4*>(&op_s[g][dq]) = acc;
    }
    __syncthreads();
    if (tid < DD) {
        float sum = 0.f;
        #pragma unroll
        for (int g = 0; g < 8; g++) sum += op_s[g][tid];
        o_s[tid] = sum * inv;
    }
    __syncthreads();

    // ---- projection partials: thread (g,d) sums dp in [g*16, g*16+16) ----
    {
        int g = tid >> 6, d = tid & 63;
        int dp0 = g * 16;
        float a0 = 0.f, a1 = 0.f;
        #pragma unroll
        for (int dp = 0; dp < 16; dp += 2) {
            a0 = fmaf(o_s[dp0 + dp],     W4[(dp0 + dp)     * DD + d], a0);
            a1 = fmaf(o_s[dp0 + dp + 1], W4[(dp0 + dp + 1) * DD + d], a1);
        }
        op_s[g][d] = a0 + a1;
    }
    __syncthreads();
    if (tid < DD)
        outg[(size_t)b * DD + tid] =
            (op_s[0][tid] + op_s[1][tid]) + (op_s[2][tid] + op_s[3][tid]) + b4[tid];
}

extern "C" void kernel_launch(void* const* d_in, const int* in_sizes, int n_in,
                              void* d_out, int out_size)
{
    const float* q  = (const float*)d_in[0];
    const float* k  = (const float*)d_in[1];
    const int*   l  = (const int*)d_in[2];
    const float* W1 = (const float*)d_in[3];
    const float* b1 = (const float*)d_in[4];
    const float* W2 = (const float*)d_in[5];
    const float* b2 = (const float*)d_in[6];
    const float* W3 = (const float*)d_in[7];
    const float* b3 = (const float*)d_in[8];
    const float* W4 = (const float*)d_in[9];
    const float* b4 = (const float*)d_in[10];
    float* out = (float*)d_out;

    const int smem_bytes = TT * KP * sizeof(float);   // 54400 B dynamic
    cudaFuncSetAttribute(din_attn_kernel,
                         cudaFuncAttributeMaxDynamicSharedMemorySize, smem_bytes);

    din_attn_kernel<<<NB, 256, smem_bytes>>>(q, k, l, W1, b1, W2, b2,
                                             W3, b3, W4, b4, out);
}